// round 9
// baseline (speedup 1.0000x reference)
#include <cuda_runtime.h>
#include <cuda_fp16.h>
#include <math.h>
#include <stdint.h>

// Problem dims (fixed)
#define BB   16
#define SS   2048
#define DD   512
#define HH   512
#define MM   (BB * SS)    // 32768 rows
#define N3H  1536         // 3*H
#define OUTC 1024         // 2*H

#define BM 128
#define BN 128
#define BK 32
#define NSTAGE 3
#define SMEM_BYTES (NSTAGE * (BM + BN) * BK * 4)   // 98304 = 96 KiB

// Scratch (allocation-free rule: __device__ globals)
__device__ __half g_ZFO_f[MM * N3H];         // 96 MiB (activated z,f,o fwd, fp16)
__device__ __half g_ZFO_b[MM * N3H];         // 96 MiB (activated z,f,o bwd, fp16)
__device__ float  g_Y1[MM * OUTC];           // 128 MiB (layer-1 input, tf32 bits)
__device__ float  g_Xc[MM * DD];             // 64 MiB  (X converted to tf32 bits)
__device__ float  g_Wt[4 * N3H * 1024];      // 24 MiB  (transposed tf32 weights, [N,K])

// ---------------------------------------------------------------------------
// helpers
// ---------------------------------------------------------------------------
__device__ __forceinline__ float to_tf32(float x) {
    uint32_t u;
    asm("cvt.rna.tf32.f32 %0, %1;" : "=r"(u) : "f"(x));
    return __uint_as_float(u);
}
__device__ __forceinline__ float ex2f(float x) {
    float y; asm("ex2.approx.f32 %0, %1;" : "=f"(y) : "f"(x)); return y;
}
__device__ __forceinline__ float rcpf(float x) {
    float y; asm("rcp.approx.f32 %0, %1;" : "=f"(y) : "f"(x)); return y;
}
__device__ __forceinline__ float sigm_fast(float x) {
    return rcpf(1.0f + ex2f(-1.4426950408889634f * x));
}
__device__ __forceinline__ float tanh_fast(float x) {
    return 2.0f * rcpf(1.0f + ex2f(-2.8853900817779268f * x)) - 1.0f;
}
__device__ __forceinline__ void cp16(void* s, const void* g) {
    uint32_t sa = (uint32_t)__cvta_generic_to_shared(s);
    asm volatile("cp.async.cg.shared.global [%0], [%1], 16;" :: "r"(sa), "l"(g));
}
__device__ __forceinline__ void mma_tf32(float* c, const uint32_t* a, const uint32_t* b) {
    asm volatile(
        "mma.sync.aligned.m16n8k8.row.col.f32.tf32.tf32.f32 "
        "{%0,%1,%2,%3}, {%4,%5,%6,%7}, {%8,%9}, {%0,%1,%2,%3};"
        : "+f"(c[0]), "+f"(c[1]), "+f"(c[2]), "+f"(c[3])
        : "r"(a[0]), "r"(a[1]), "r"(a[2]), "r"(a[3]), "r"(b[0]), "r"(b[1]));
}

// ---------------------------------------------------------------------------
// Prepass: transpose + tf32-convert weights; tf32-convert X
// ---------------------------------------------------------------------------
__global__ void transpose_cvt_kernel(const float* __restrict__ W,
                                     float* __restrict__ Wt, int K)
{
    __shared__ float tile[32][33];
    const int kb = blockIdx.x * 32;
    const int nb = blockIdx.y * 32;
    const int tx = threadIdx.x, ty = threadIdx.y;  // 32 x 8
#pragma unroll
    for (int r = 0; r < 32; r += 8)
        tile[ty + r][tx] = W[(size_t)(kb + ty + r) * N3H + nb + tx];
    __syncthreads();
#pragma unroll
    for (int r = 0; r < 32; r += 8)
        Wt[(size_t)(nb + ty + r) * K + kb + tx] = to_tf32(tile[tx][ty + r]);
}

__global__ void cvt_tf32_kernel(const float* __restrict__ in, float* __restrict__ out, int n4)
{
    int i = blockIdx.x * blockDim.x + threadIdx.x;
    if (i < n4) {
        float4 v = ((const float4*)in)[i];
        v.x = to_tf32(v.x); v.y = to_tf32(v.y); v.z = to_tf32(v.z); v.w = to_tf32(v.w);
        ((float4*)out)[i] = v;
    }
}

// ---------------------------------------------------------------------------
// TF32 tensor-core GEMM + bias + activation -> fp16 output:
//   C[M, 1536] = act( A[M,K] @ Wt[1536,K]^T + bias )
// 128x128x32 tiles, 3-stage cp.async pipeline, 8 warps (2M x 4N),
// m16n8k8 tf32 MMA, XOR-swizzled smem (conflict-free).
// ---------------------------------------------------------------------------
template <int K>
__global__ void __launch_bounds__(256, 2) gemm_tf32_kernel(
    const float* __restrict__ A,
    const float* __restrict__ Bt,     // [1536, K]
    const float* __restrict__ bias,
    __half* __restrict__ C)
{
    extern __shared__ float smem[];
    float* As = smem;                        // [NSTAGE][BM*BK]
    float* Bs = smem + NSTAGE * BM * BK;     // [NSTAGE][BN*BK]

    const int tid = threadIdx.x;
    const int warp = tid >> 5;
    const int lane = tid & 31;
    const int g = lane >> 2;          // 0..7
    const int t = lane & 3;           // 0..3
    const int wm = warp & 1;          // 2 warps M
    const int wn = warp >> 1;         // 4 warps N
    const int blockM = blockIdx.y * BM;
    const int blockN = blockIdx.x * BN;

    float acc[4][4][4];
#pragma unroll
    for (int i = 0; i < 4; i++)
#pragma unroll
        for (int j = 0; j < 4; j++)
#pragma unroll
            for (int q = 0; q < 4; q++) acc[i][j][q] = 0.0f;

    // stage loader: per operand 128 rows x 8 float4 (1024 slots, 4 iters x 256)
    auto load_stage = [&](int buf, int k0) {
#pragma unroll
        for (int it = 0; it < 4; it++) {
            const int idx = tid + it * 256;
            const int row = idx >> 3;                 // 0..127
            const int c4  = idx & 7;                  // 0..7
            const int scol = (c4 * 4) ^ ((row * 4) & 31);
            cp16(&As[buf * BM * BK + row * BK + scol],
                 &A[(size_t)(blockM + row) * K + k0 + c4 * 4]);
        }
#pragma unroll
        for (int it = 0; it < 4; it++) {
            const int idx = tid + it * 256;
            const int row = idx >> 3;
            const int c4  = idx & 7;
            const int scol = (c4 * 4) ^ ((row * 4) & 31);
            cp16(&Bs[buf * BM * BK + row * BK + scol],
                 &Bt[(size_t)(blockN + row) * K + k0 + c4 * 4]);
        }
        asm volatile("cp.async.commit_group;" ::: "memory");
    };

    const int ntiles = K / BK;
    load_stage(0, 0);
    load_stage(1, BK);

    for (int kt = 0; kt < ntiles; kt++) {
        if (kt + 2 < ntiles) {
            load_stage((kt + 2) % NSTAGE, (kt + 2) * BK);
            asm volatile("cp.async.wait_group 2;" ::: "memory");
        } else if (kt + 1 < ntiles) {
            asm volatile("cp.async.wait_group 1;" ::: "memory");
        } else {
            asm volatile("cp.async.wait_group 0;" ::: "memory");
        }
        __syncthreads();

        const float* Ab = &As[(kt % NSTAGE) * BM * BK];
        const float* Bb = &Bs[(kt % NSTAGE) * BM * BK];

#pragma unroll
        for (int kk = 0; kk < BK; kk += 8) {
            uint32_t af[4][4], bf[4][2];
#pragma unroll
            for (int i = 0; i < 4; i++) {
                const int m0 = wm * 64 + i * 16 + g;
                const int m1 = m0 + 8;
                const int s0 = (m0 * 4) & 31;
                const int s1 = (m1 * 4) & 31;
                af[i][0] = __float_as_uint(Ab[m0 * BK + ((kk + t) ^ s0)]);
                af[i][1] = __float_as_uint(Ab[m1 * BK + ((kk + t) ^ s1)]);
                af[i][2] = __float_as_uint(Ab[m0 * BK + ((kk + t + 4) ^ s0)]);
                af[i][3] = __float_as_uint(Ab[m1 * BK + ((kk + t + 4) ^ s1)]);
            }
#pragma unroll
            for (int j = 0; j < 4; j++) {
                const int n0 = wn * 32 + j * 8 + g;
                const int s0 = (n0 * 4) & 31;
                bf[j][0] = __float_as_uint(Bb[n0 * BK + ((kk + t) ^ s0)]);
                bf[j][1] = __float_as_uint(Bb[n0 * BK + ((kk + t + 4) ^ s0)]);
            }
#pragma unroll
            for (int i = 0; i < 4; i++)
#pragma unroll
                for (int j = 0; j < 4; j++)
                    mma_tf32(acc[i][j], af[i], bf[j]);
        }
        __syncthreads();
    }

    // Epilogue: bias + activation + fp16 store. Boundary at col 512 is
    // block-uniform (BN=128 divides 512).
    const bool is_tanh = (blockN < HH);
#pragma unroll
    for (int i = 0; i < 4; i++) {
        const int row0 = blockM + wm * 64 + i * 16 + g;
#pragma unroll
        for (int j = 0; j < 4; j++) {
            const int col = blockN + wn * 32 + j * 8 + 2 * t;
            const float b0 = bias[col], b1 = bias[col + 1];
            float v[4] = {acc[i][j][0] + b0, acc[i][j][1] + b1,
                          acc[i][j][2] + b0, acc[i][j][3] + b1};
            if (is_tanh) {
#pragma unroll
                for (int q = 0; q < 4; q++) v[q] = tanh_fast(v[q]);
            } else {
#pragma unroll
                for (int q = 0; q < 4; q++) v[q] = sigm_fast(v[q]);
            }
            *(__half2*)&C[(size_t)row0 * N3H + col]       = __floats2half2_rn(v[0], v[1]);
            *(__half2*)&C[(size_t)(row0 + 8) * N3H + col] = __floats2half2_rn(v[2], v[3]);
        }
    }
}

// ---------------------------------------------------------------------------
// fo-pooling scan, both directions in one launch; fp16 inputs.
// One thread per (dir, b, h). CVT: tf32-round output (feeds next tf32 GEMM).
// ---------------------------------------------------------------------------
template <bool CVT>
__global__ void __launch_bounds__(256) scan_kernel(
    const __half* __restrict__ ZFOf,
    const __half* __restrict__ ZFOb,
    float* __restrict__ Y)
{
    const int tt  = blockIdx.x * blockDim.x + threadIdx.x;  // 0..16383
    const int dir = tt >> 13;
    const int b   = (tt >> 9) & 15;
    const int h   = tt & 511;

    const __half* __restrict__ Z = dir ? ZFOb : ZFOf;
    const size_t rowBase = (size_t)b * SS;
    const int outOff = dir * HH + h;

    float c = 0.0f;
    constexpr int CH = 8;
    for (int sc = 0; sc < SS; sc += CH) {
        float zv[CH], fv[CH], ov[CH];
#pragma unroll
        for (int j = 0; j < CH; j++) {
            const int s = dir ? (SS - 1 - (sc + j)) : (sc + j);
            const size_t idx = (rowBase + s) * N3H + h;
            zv[j] = __half2float(Z[idx]);
            fv[j] = __half2float(Z[idx + 512]);
            ov[j] = __half2float(Z[idx + 1024]);
        }
#pragma unroll
        for (int j = 0; j < CH; j++) {
            c = fv[j] * c + (1.0f - fv[j]) * zv[j];
            const int s = dir ? (SS - 1 - (sc + j)) : (sc + j);
            float out = ov[j] * c;
            if (CVT) out = to_tf32(out);
            Y[(rowBase + s) * OUTC + outOff] = out;
        }
    }
}

// ---------------------------------------------------------------------------
extern "C" void kernel_launch(void* const* d_in, const int* in_sizes, int n_in,
                              void* d_out, int out_size)
{
    const float* X     = (const float*)d_in[0];
    // d_in[1] = seqlens (unused, per reference)
    const float* W_fw0 = (const float*)d_in[2];
    const float* b_fw0 = (const float*)d_in[3];
    const float* W_bw0 = (const float*)d_in[4];
    const float* b_bw0 = (const float*)d_in[5];
    const float* W_fw1 = (const float*)d_in[6];
    const float* b_fw1 = (const float*)d_in[7];
    const float* W_bw1 = (const float*)d_in[8];
    const float* b_bw1 = (const float*)d_in[9];
    float* out = (float*)d_out;

    __half *ZFOf, *ZFOb;
    float *Y1, *Xc, *Wt;
    cudaGetSymbolAddress((void**)&ZFOf, g_ZFO_f);
    cudaGetSymbolAddress((void**)&ZFOb, g_ZFO_b);
    cudaGetSymbolAddress((void**)&Y1,  g_Y1);
    cudaGetSymbolAddress((void**)&Xc,  g_Xc);
    cudaGetSymbolAddress((void**)&Wt,  g_Wt);

    float* Wt0f = Wt;
    float* Wt0b = Wt + (size_t)N3H * 1024;
    float* Wt1f = Wt + (size_t)N3H * 1024 * 2;
    float* Wt1b = Wt + (size_t)N3H * 1024 * 3;

    cudaFuncSetAttribute(gemm_tf32_kernel<DD>,
                         cudaFuncAttributeMaxDynamicSharedMemorySize, SMEM_BYTES);
    cudaFuncSetAttribute(gemm_tf32_kernel<OUTC>,
                         cudaFuncAttributeMaxDynamicSharedMemorySize, SMEM_BYTES);

    // Prepass: transpose+tf32 weights, tf32-convert X
    {
        dim3 blk(32, 8);
        transpose_cvt_kernel<<<dim3(DD / 32,  N3H / 32), blk>>>(W_fw0, Wt0f, DD);
        transpose_cvt_kernel<<<dim3(DD / 32,  N3H / 32), blk>>>(W_bw0, Wt0b, DD);
        transpose_cvt_kernel<<<dim3(OUTC / 32, N3H / 32), blk>>>(W_fw1, Wt1f, OUTC);
        transpose_cvt_kernel<<<dim3(OUTC / 32, N3H / 32), blk>>>(W_bw1, Wt1b, OUTC);
        const int n4 = MM * DD / 4;
        cvt_tf32_kernel<<<(n4 + 255) / 256, 256>>>(X, Xc, n4);
    }

    dim3 gemmGrid(N3H / BN, MM / BM);   // 12 x 256
    dim3 gemmBlock(256);
    dim3 scanGrid(16384 / 256);
    dim3 scanBlock(256);

    // Layer 0
    gemm_tf32_kernel<DD><<<gemmGrid, gemmBlock, SMEM_BYTES>>>(Xc, Wt0f, b_fw0, ZFOf);
    gemm_tf32_kernel<DD><<<gemmGrid, gemmBlock, SMEM_BYTES>>>(Xc, Wt0b, b_bw0, ZFOb);
    scan_kernel<true><<<scanGrid, scanBlock>>>(ZFOf, ZFOb, Y1);

    // Layer 1
    gemm_tf32_kernel<OUTC><<<gemmGrid, gemmBlock, SMEM_BYTES>>>(Y1, Wt1f, b_fw1, ZFOf);
    gemm_tf32_kernel<OUTC><<<gemmGrid, gemmBlock, SMEM_BYTES>>>(Y1, Wt1b, b_bw1, ZFOb);
    scan_kernel<false><<<scanGrid, scanBlock>>>(ZFOf, ZFOb, out);
}

// round 12
// speedup vs baseline: 1.9174x; 1.9174x over previous
#include <cuda_runtime.h>
#include <cuda_fp16.h>
#include <math.h>
#include <stdint.h>

// Problem dims (fixed)
#define BB   16
#define SS   2048
#define DD   512
#define HH   512
#define MM   (BB * SS)    // 32768 rows
#define N3H  1536         // 3*H
#define OUTC 1024         // 2*H

#define BM 128
#define BN 128
#define BK 64
#define NSTAGE 3
// per stage: A 128x64 fp16 = 16KB, B 128x64 fp16 = 16KB
#define STAGE_A_BYTES (BM * BK * 2)                 // 16384
#define STAGE_B_BYTES (BN * BK * 2)                 // 16384
#define SMEM_BYTES (NSTAGE * (STAGE_A_BYTES + STAGE_B_BYTES))  // 98304 = 96 KiB

// Scratch (allocation-free rule: __device__ globals)
__device__ __half g_ZFO_f[MM * N3H];         // 96 MiB (activated z,f,o fwd)
__device__ __half g_ZFO_b[MM * N3H];         // 96 MiB (activated z,f,o bwd)
__device__ __half g_Y1[MM * OUTC];           // 64 MiB (layer-1 input, fp16)
__device__ __half g_Xh[MM * DD];             // 32 MiB (X in fp16)
__device__ __half g_Wt[4 * N3H * 1024];      // 12 MiB (transposed fp16 weights, [N,K])

// ---------------------------------------------------------------------------
// helpers
// ---------------------------------------------------------------------------
__device__ __forceinline__ float ex2f(float x) {
    float y; asm("ex2.approx.f32 %0, %1;" : "=f"(y) : "f"(x)); return y;
}
__device__ __forceinline__ float rcpf(float x) {
    float y; asm("rcp.approx.f32 %0, %1;" : "=f"(y) : "f"(x)); return y;
}
__device__ __forceinline__ float sigm_fast(float x) {
    return rcpf(1.0f + ex2f(-1.4426950408889634f * x));
}
__device__ __forceinline__ float tanh_fast(float x) {
    return 2.0f * rcpf(1.0f + ex2f(-2.8853900817779268f * x)) - 1.0f;
}
__device__ __forceinline__ void cp16(void* s, const void* g) {
    uint32_t sa = (uint32_t)__cvta_generic_to_shared(s);
    asm volatile("cp.async.cg.shared.global [%0], [%1], 16;" :: "r"(sa), "l"(g));
}
// fp16 MMA: D(f32) = A(f16) * B(f16) + D, m16n8k16
__device__ __forceinline__ void mma_f16(float* c, const uint32_t* a, const uint32_t* b) {
    asm volatile(
        "mma.sync.aligned.m16n8k16.row.col.f32.f16.f16.f32 "
        "{%0,%1,%2,%3}, {%4,%5,%6,%7}, {%8,%9}, {%0,%1,%2,%3};"
        : "+f"(c[0]), "+f"(c[1]), "+f"(c[2]), "+f"(c[3])
        : "r"(a[0]), "r"(a[1]), "r"(a[2]), "r"(a[3]), "r"(b[0]), "r"(b[1]));
}

// ---------------------------------------------------------------------------
// Prepass: transpose + fp16-convert weights: W [K,1536] -> Wt [1536,K] fp16
// ---------------------------------------------------------------------------
__global__ void transpose_cvt_kernel(const float* __restrict__ W,
                                     __half* __restrict__ Wt, int K)
{
    __shared__ float tile[32][33];
    const int kb = blockIdx.x * 32;
    const int nb = blockIdx.y * 32;
    const int tx = threadIdx.x, ty = threadIdx.y;  // 32 x 8
#pragma unroll
    for (int r = 0; r < 32; r += 8)
        tile[ty + r][tx] = W[(size_t)(kb + ty + r) * N3H + nb + tx];
    __syncthreads();
#pragma unroll
    for (int r = 0; r < 32; r += 8)
        Wt[(size_t)(nb + ty + r) * K + kb + tx] = __float2half_rn(tile[tx][ty + r]);
}

__global__ void cvt_half_kernel(const float* __restrict__ in, __half* __restrict__ out, int n4)
{
    int i = blockIdx.x * blockDim.x + threadIdx.x;
    if (i < n4) {
        float4 v = ((const float4*)in)[i];
        __half2 h0 = __floats2half2_rn(v.x, v.y);
        __half2 h1 = __floats2half2_rn(v.z, v.w);
        ((__half2*)out)[i * 2]     = h0;
        ((__half2*)out)[i * 2 + 1] = h1;
    }
}

// ---------------------------------------------------------------------------
// FP16 tensor-core GEMM + bias + activation -> fp16 output:
//   C[M, 1536] = act( A[M,K] @ Wt[1536,K]^T + bias )
// 128x128x64 tiles, 3-stage cp.async, 8 warps (2M x 4N), m16n8k16 fp16 MMA,
// fp32 accum, SW128-style swizzle (rows of 128B = 64 halves; 16B chunk c at
// row r lands at chunk c^(r&7)). Conflict-free for 16B writes and b32 reads.
// ---------------------------------------------------------------------------
template <int K>
__global__ void __launch_bounds__(256, 2) gemm_f16_kernel(
    const __half* __restrict__ A,
    const __half* __restrict__ Bt,     // [1536, K]
    const float* __restrict__ bias,
    __half* __restrict__ C)
{
    extern __shared__ char smem[];
    char* Asm = smem;                             // [NSTAGE][16KB]
    char* Bsm = smem + NSTAGE * STAGE_A_BYTES;    // [NSTAGE][16KB]

    const int tid = threadIdx.x;
    const int warp = tid >> 5;
    const int lane = tid & 31;
    const int g = lane >> 2;          // 0..7
    const int t = lane & 3;           // 0..3
    const int wm = warp & 1;          // 2 warps M
    const int wn = warp >> 1;         // 4 warps N
    const int blockM = blockIdx.y * BM;
    const int blockN = blockIdx.x * BN;

    float acc[4][4][4];
#pragma unroll
    for (int i = 0; i < 4; i++)
#pragma unroll
        for (int j = 0; j < 4; j++)
#pragma unroll
            for (int q = 0; q < 4; q++) acc[i][j][q] = 0.0f;

    // stage loader: per operand 128 rows x 8 chunks of 16B (8 halves each)
    auto load_stage = [&](int buf, int k0) {
#pragma unroll
        for (int it = 0; it < 4; it++) {
            const int idx = tid + it * 256;
            const int row = idx >> 3;                 // 0..127
            const int c4  = idx & 7;                  // 0..7
            const int off = row * 128 + ((c4 ^ (row & 7)) << 4);
            cp16(Asm + buf * STAGE_A_BYTES + off,
                 &A[(size_t)(blockM + row) * K + k0 + c4 * 8]);
        }
#pragma unroll
        for (int it = 0; it < 4; it++) {
            const int idx = tid + it * 256;
            const int row = idx >> 3;
            const int c4  = idx & 7;
            const int off = row * 128 + ((c4 ^ (row & 7)) << 4);
            cp16(Bsm + buf * STAGE_B_BYTES + off,
                 &Bt[(size_t)(blockN + row) * K + k0 + c4 * 8]);
        }
        asm volatile("cp.async.commit_group;" ::: "memory");
    };

    const int ntiles = K / BK;
    load_stage(0, 0);
    load_stage(1, BK);

    for (int kt = 0; kt < ntiles; kt++) {
        if (kt + 2 < ntiles) {
            load_stage((kt + 2) % NSTAGE, (kt + 2) * BK);
            asm volatile("cp.async.wait_group 2;" ::: "memory");
        } else if (kt + 1 < ntiles) {
            asm volatile("cp.async.wait_group 1;" ::: "memory");
        } else {
            asm volatile("cp.async.wait_group 0;" ::: "memory");
        }
        __syncthreads();

        const char* Ab = Asm + (kt % NSTAGE) * STAGE_A_BYTES;
        const char* Bb = Bsm + (kt % NSTAGE) * STAGE_B_BYTES;

#pragma unroll
        for (int kk = 0; kk < BK; kk += 16) {
            const int ch0 = kk >> 3;          // chunk of k window low half
            uint32_t af[4][4], bf[4][2];
#pragma unroll
            for (int i = 0; i < 4; i++) {
                const int m0 = wm * 64 + i * 16 + g;
                const int m1 = m0 + 8;
                const int r0 = m0 * 128, r1 = m1 * 128;
                const int s00 = ((ch0     ^ (m0 & 7)) << 4) + 4 * t;
                const int s01 = (((ch0+1) ^ (m0 & 7)) << 4) + 4 * t;
                const int s10 = ((ch0     ^ (m1 & 7)) << 4) + 4 * t;
                const int s11 = (((ch0+1) ^ (m1 & 7)) << 4) + 4 * t;
                af[i][0] = *(const uint32_t*)(Ab + r0 + s00);
                af[i][1] = *(const uint32_t*)(Ab + r1 + s10);
                af[i][2] = *(const uint32_t*)(Ab + r0 + s01);
                af[i][3] = *(const uint32_t*)(Ab + r1 + s11);
            }
#pragma unroll
            for (int j = 0; j < 4; j++) {
                const int n0 = wn * 32 + j * 8 + g;
                const int rn = n0 * 128;
                bf[j][0] = *(const uint32_t*)(Bb + rn + ((ch0     ^ (n0 & 7)) << 4) + 4 * t);
                bf[j][1] = *(const uint32_t*)(Bb + rn + (((ch0+1) ^ (n0 & 7)) << 4) + 4 * t);
            }
#pragma unroll
            for (int i = 0; i < 4; i++)
#pragma unroll
                for (int j = 0; j < 4; j++)
                    mma_f16(acc[i][j], af[i], bf[j]);
        }
        __syncthreads();
    }

    // Epilogue: bias + activation + fp16 store. Boundary at col 512 is
    // block-uniform (BN=128 divides 512).
    const bool is_tanh = (blockN < HH);
#pragma unroll
    for (int i = 0; i < 4; i++) {
        const int row0 = blockM + wm * 64 + i * 16 + g;
#pragma unroll
        for (int j = 0; j < 4; j++) {
            const int col = blockN + wn * 32 + j * 8 + 2 * t;
            const float b0 = bias[col], b1 = bias[col + 1];
            float v[4] = {acc[i][j][0] + b0, acc[i][j][1] + b1,
                          acc[i][j][2] + b0, acc[i][j][3] + b1};
            if (is_tanh) {
#pragma unroll
                for (int q = 0; q < 4; q++) v[q] = tanh_fast(v[q]);
            } else {
#pragma unroll
                for (int q = 0; q < 4; q++) v[q] = sigm_fast(v[q]);
            }
            *(__half2*)&C[(size_t)row0 * N3H + col]       = __floats2half2_rn(v[0], v[1]);
            *(__half2*)&C[(size_t)(row0 + 8) * N3H + col] = __floats2half2_rn(v[2], v[3]);
        }
    }
}

// ---------------------------------------------------------------------------
// fo-pooling scan, both directions in one launch; fp16 in, OutT out.
// One thread per (dir, b, h).
// ---------------------------------------------------------------------------
template <typename OutT>
__global__ void __launch_bounds__(256) scan_kernel(
    const __half* __restrict__ ZFOf,
    const __half* __restrict__ ZFOb,
    OutT* __restrict__ Y)
{
    const int tt  = blockIdx.x * blockDim.x + threadIdx.x;  // 0..16383
    const int dir = tt >> 13;
    const int b   = (tt >> 9) & 15;
    const int h   = tt & 511;

    const __half* __restrict__ Z = dir ? ZFOb : ZFOf;
    const size_t rowBase = (size_t)b * SS;
    const int outOff = dir * HH + h;

    float c = 0.0f;
    constexpr int CH = 8;
    for (int sc = 0; sc < SS; sc += CH) {
        float zv[CH], fv[CH], ov[CH];
#pragma unroll
        for (int j = 0; j < CH; j++) {
            const int s = dir ? (SS - 1 - (sc + j)) : (sc + j);
            const size_t idx = (rowBase + s) * N3H + h;
            zv[j] = __half2float(Z[idx]);
            fv[j] = __half2float(Z[idx + 512]);
            ov[j] = __half2float(Z[idx + 1024]);
        }
#pragma unroll
        for (int j = 0; j < CH; j++) {
            c = fv[j] * c + (1.0f - fv[j]) * zv[j];
            const int s = dir ? (SS - 1 - (sc + j)) : (sc + j);
            Y[(rowBase + s) * OUTC + outOff] = (OutT)(ov[j] * c);
        }
    }
}

// ---------------------------------------------------------------------------
extern "C" void kernel_launch(void* const* d_in, const int* in_sizes, int n_in,
                              void* d_out, int out_size)
{
    const float* X     = (const float*)d_in[0];
    // d_in[1] = seqlens (unused, per reference)
    const float* W_fw0 = (const float*)d_in[2];
    const float* b_fw0 = (const float*)d_in[3];
    const float* W_bw0 = (const float*)d_in[4];
    const float* b_bw0 = (const float*)d_in[5];
    const float* W_fw1 = (const float*)d_in[6];
    const float* b_fw1 = (const float*)d_in[7];
    const float* W_bw1 = (const float*)d_in[8];
    const float* b_bw1 = (const float*)d_in[9];
    float* out = (float*)d_out;

    __half *ZFOf, *ZFOb, *Y1, *Xh, *Wt;
    cudaGetSymbolAddress((void**)&ZFOf, g_ZFO_f);
    cudaGetSymbolAddress((void**)&ZFOb, g_ZFO_b);
    cudaGetSymbolAddress((void**)&Y1,  g_Y1);
    cudaGetSymbolAddress((void**)&Xh,  g_Xh);
    cudaGetSymbolAddress((void**)&Wt,  g_Wt);

    __half* Wt0f = Wt;
    __half* Wt0b = Wt + (size_t)N3H * 1024;
    __half* Wt1f = Wt + (size_t)N3H * 1024 * 2;
    __half* Wt1b = Wt + (size_t)N3H * 1024 * 3;

    cudaFuncSetAttribute(gemm_f16_kernel<DD>,
                         cudaFuncAttributeMaxDynamicSharedMemorySize, SMEM_BYTES);
    cudaFuncSetAttribute(gemm_f16_kernel<OUTC>,
                         cudaFuncAttributeMaxDynamicSharedMemorySize, SMEM_BYTES);

    // Prepass: transpose+fp16 weights, fp16-convert X
    {
        dim3 blk(32, 8);
        transpose_cvt_kernel<<<dim3(DD / 32,  N3H / 32), blk>>>(W_fw0, Wt0f, DD);
        transpose_cvt_kernel<<<dim3(DD / 32,  N3H / 32), blk>>>(W_bw0, Wt0b, DD);
        transpose_cvt_kernel<<<dim3(OUTC / 32, N3H / 32), blk>>>(W_fw1, Wt1f, OUTC);
        transpose_cvt_kernel<<<dim3(OUTC / 32, N3H / 32), blk>>>(W_bw1, Wt1b, OUTC);
        const int n4 = MM * DD / 4;
        cvt_half_kernel<<<(n4 + 255) / 256, 256>>>(X, Xh, n4);
    }

    dim3 gemmGrid(N3H / BN, MM / BM);   // 12 x 256
    dim3 gemmBlock(256);
    dim3 scanGrid(16384 / 256);
    dim3 scanBlock(256);

    // Layer 0
    gemm_f16_kernel<DD><<<gemmGrid, gemmBlock, SMEM_BYTES>>>(Xh, Wt0f, b_fw0, ZFOf);
    gemm_f16_kernel<DD><<<gemmGrid, gemmBlock, SMEM_BYTES>>>(Xh, Wt0b, b_bw0, ZFOb);
    scan_kernel<__half><<<scanGrid, scanBlock>>>(ZFOf, ZFOb, Y1);

    // Layer 1
    gemm_f16_kernel<OUTC><<<gemmGrid, gemmBlock, SMEM_BYTES>>>(Y1, Wt1f, b_fw1, ZFOf);
    gemm_f16_kernel<OUTC><<<gemmGrid, gemmBlock, SMEM_BYTES>>>(Y1, Wt1b, b_bw1, ZFOb);
    scan_kernel<float><<<scanGrid, scanBlock>>>(ZFOf, ZFOb, out);
}

// round 13
// speedup vs baseline: 2.0343x; 1.0610x over previous
#include <cuda_runtime.h>
#include <cuda_fp16.h>
#include <math.h>
#include <stdint.h>

// Problem dims (fixed)
#define BB   16
#define SS   2048
#define DD   512
#define HH   512
#define MM   (BB * SS)    // 32768 rows
#define N3H  1536         // 3*H
#define OUTC 1024         // 2*H

#define BM 128
#define BN 128
#define BK 64
#define NSTAGE 3
// per stage: A 128x64 fp16 = 16KB, B 128x64 fp16 = 16KB
#define STAGE_A_BYTES (BM * BK * 2)                 // 16384
#define STAGE_B_BYTES (BN * BK * 2)                 // 16384
#define SMEM_BYTES (NSTAGE * (STAGE_A_BYTES + STAGE_B_BYTES))  // 98304 = 96 KiB

// Scratch (allocation-free rule: __device__ globals)
__device__ __half g_ZFO_f[MM * N3H];         // 96 MiB (activated z,f,o fwd)
__device__ __half g_ZFO_b[MM * N3H];         // 96 MiB (activated z,f,o bwd)
__device__ __half g_Y1[MM * OUTC];           // 64 MiB (layer-1 input, fp16)
__device__ __half g_Xh[MM * DD];             // 32 MiB (X in fp16)
__device__ __half g_Wt[4 * N3H * 1024];      // 12 MiB (transposed fp16 weights, [N,K])

// ---------------------------------------------------------------------------
// helpers
// ---------------------------------------------------------------------------
__device__ __forceinline__ float ex2f(float x) {
    float y; asm("ex2.approx.f32 %0, %1;" : "=f"(y) : "f"(x)); return y;
}
__device__ __forceinline__ float rcpf(float x) {
    float y; asm("rcp.approx.f32 %0, %1;" : "=f"(y) : "f"(x)); return y;
}
__device__ __forceinline__ float sigm_fast(float x) {
    return rcpf(1.0f + ex2f(-1.4426950408889634f * x));
}
__device__ __forceinline__ float tanh_fast(float x) {
    return 2.0f * rcpf(1.0f + ex2f(-2.8853900817779268f * x)) - 1.0f;
}
__device__ __forceinline__ void cp16(void* s, const void* g) {
    uint32_t sa = (uint32_t)__cvta_generic_to_shared(s);
    asm volatile("cp.async.cg.shared.global [%0], [%1], 16;" :: "r"(sa), "l"(g));
}
// fp16 MMA: D(f32) = A(f16) * B(f16) + D, m16n8k16
__device__ __forceinline__ void mma_f16(float* c, const uint32_t* a, const uint32_t* b) {
    asm volatile(
        "mma.sync.aligned.m16n8k16.row.col.f32.f16.f16.f32 "
        "{%0,%1,%2,%3}, {%4,%5,%6,%7}, {%8,%9}, {%0,%1,%2,%3};"
        : "+f"(c[0]), "+f"(c[1]), "+f"(c[2]), "+f"(c[3])
        : "r"(a[0]), "r"(a[1]), "r"(a[2]), "r"(a[3]), "r"(b[0]), "r"(b[1]));
}
__device__ __forceinline__ void ldsm_x4(uint32_t& r0, uint32_t& r1, uint32_t& r2,
                                        uint32_t& r3, uint32_t addr) {
    asm volatile("ldmatrix.sync.aligned.m8n8.x4.shared.b16 {%0,%1,%2,%3}, [%4];"
                 : "=r"(r0), "=r"(r1), "=r"(r2), "=r"(r3) : "r"(addr));
}

// ---------------------------------------------------------------------------
// Prepass: transpose + fp16-convert weights: W [K,1536] -> Wt [1536,K] fp16
// ---------------------------------------------------------------------------
__global__ void transpose_cvt_kernel(const float* __restrict__ W,
                                     __half* __restrict__ Wt, int K)
{
    __shared__ float tile[32][33];
    const int kb = blockIdx.x * 32;
    const int nb = blockIdx.y * 32;
    const int tx = threadIdx.x, ty = threadIdx.y;  // 32 x 8
#pragma unroll
    for (int r = 0; r < 32; r += 8)
        tile[ty + r][tx] = W[(size_t)(kb + ty + r) * N3H + nb + tx];
    __syncthreads();
#pragma unroll
    for (int r = 0; r < 32; r += 8)
        Wt[(size_t)(nb + ty + r) * K + kb + tx] = __float2half_rn(tile[tx][ty + r]);
}

__global__ void cvt_half_kernel(const float* __restrict__ in, __half* __restrict__ out, int n4)
{
    int i = blockIdx.x * blockDim.x + threadIdx.x;
    if (i < n4) {
        float4 v = ((const float4*)in)[i];
        __half2 h0 = __floats2half2_rn(v.x, v.y);
        __half2 h1 = __floats2half2_rn(v.z, v.w);
        ((__half2*)out)[i * 2]     = h0;
        ((__half2*)out)[i * 2 + 1] = h1;
    }
}

// ---------------------------------------------------------------------------
// FP16 tensor-core GEMM + bias + activation -> fp16 output:
//   C[M, 1536] = act( A[M,K] @ Wt[1536,K]^T + bias )
// 128x128x64 tiles, 3-stage cp.async, 8 warps (2M x 4N), m16n8k16 fp16 MMA,
// fp32 accum, swizzled smem, ldmatrix.x4 fragment loads (6 LDSM + 16 MMA
// per kk-step vs 24 LDS before).
// ---------------------------------------------------------------------------
template <int K>
__global__ void __launch_bounds__(256, 2) gemm_f16_kernel(
    const __half* __restrict__ A,
    const __half* __restrict__ Bt,     // [1536, K]
    const float* __restrict__ bias,
    __half* __restrict__ C)
{
    extern __shared__ char smem[];
    char* Asm = smem;                             // [NSTAGE][16KB]
    char* Bsm = smem + NSTAGE * STAGE_A_BYTES;    // [NSTAGE][16KB]
    const uint32_t Asm0 = (uint32_t)__cvta_generic_to_shared(Asm);
    const uint32_t Bsm0 = (uint32_t)__cvta_generic_to_shared(Bsm);

    const int tid = threadIdx.x;
    const int warp = tid >> 5;
    const int lane = tid & 31;
    const int g = lane >> 2;          // 0..7
    const int t = lane & 3;           // 0..3
    const int wm = warp & 1;          // 2 warps M
    const int wn = warp >> 1;         // 4 warps N
    const int blockM = blockIdx.y * BM;
    const int blockN = blockIdx.x * BN;

    // ldmatrix lane roles
    const int lrow = lane & 7;        // row within 8-row matrix
    const int sel  = lane >> 3;       // matrix index 0..3

    // A: matrices {a0:(m,ch0) a1:(m+8,ch0) a2:(m,ch0+1) a3:(m+8,ch0+1)}
    //    -> mrow = base + lrow + (sel&1)*8 ; ch = ch0 + (sel>>1)
    const int a_mrow_off = lrow + (sel & 1) * 8;   // + wm*64 + i*16
    const int a_choff    = sel >> 1;
    // B: matrices {bj0:(n,ch0) bj1:(n,ch0+1) b(j+1)0:(n+8,ch0) b(j+1)1:(n+8,ch0+1)}
    //    -> nrow = base + lrow + (sel>>1)*8 ; ch = ch0 + (sel&1)
    const int b_nrow_off = lrow + (sel >> 1) * 8;  // + wn*32 + jj*8
    const int b_choff    = sel & 1;

    float acc[4][4][4];
#pragma unroll
    for (int i = 0; i < 4; i++)
#pragma unroll
        for (int j = 0; j < 4; j++)
#pragma unroll
            for (int q = 0; q < 4; q++) acc[i][j][q] = 0.0f;

    // stage loader: per operand 128 rows x 8 chunks of 16B (8 halves each)
    auto load_stage = [&](int buf, int k0) {
#pragma unroll
        for (int it = 0; it < 4; it++) {
            const int idx = tid + it * 256;
            const int row = idx >> 3;                 // 0..127
            const int c4  = idx & 7;                  // 0..7
            const int off = row * 128 + ((c4 ^ (row & 7)) << 4);
            cp16(Asm + buf * STAGE_A_BYTES + off,
                 &A[(size_t)(blockM + row) * K + k0 + c4 * 8]);
        }
#pragma unroll
        for (int it = 0; it < 4; it++) {
            const int idx = tid + it * 256;
            const int row = idx >> 3;
            const int c4  = idx & 7;
            const int off = row * 128 + ((c4 ^ (row & 7)) << 4);
            cp16(Bsm + buf * STAGE_B_BYTES + off,
                 &Bt[(size_t)(blockN + row) * K + k0 + c4 * 8]);
        }
        asm volatile("cp.async.commit_group;" ::: "memory");
    };

    const int ntiles = K / BK;
    load_stage(0, 0);
    load_stage(1, BK);

    for (int kt = 0; kt < ntiles; kt++) {
        if (kt + 2 < ntiles) {
            load_stage((kt + 2) % NSTAGE, (kt + 2) * BK);
            asm volatile("cp.async.wait_group 2;" ::: "memory");
        } else if (kt + 1 < ntiles) {
            asm volatile("cp.async.wait_group 1;" ::: "memory");
        } else {
            asm volatile("cp.async.wait_group 0;" ::: "memory");
        }
        __syncthreads();

        const uint32_t Ab = Asm0 + (kt % NSTAGE) * STAGE_A_BYTES;
        const uint32_t Bb = Bsm0 + (kt % NSTAGE) * STAGE_B_BYTES;

#pragma unroll
        for (int kk = 0; kk < BK; kk += 16) {
            const int ch0 = kk >> 3;          // 0,2,4,6
            uint32_t af[4][4], bf[4][2];
#pragma unroll
            for (int i = 0; i < 4; i++) {
                const int mrow = wm * 64 + i * 16 + a_mrow_off;
                const int ch   = ch0 + a_choff;
                const uint32_t addr = Ab + mrow * 128 + ((ch ^ (mrow & 7)) << 4);
                ldsm_x4(af[i][0], af[i][1], af[i][2], af[i][3], addr);
            }
#pragma unroll
            for (int jj = 0; jj < 4; jj += 2) {
                const int nrow = wn * 32 + jj * 8 + b_nrow_off;
                const int ch   = ch0 + b_choff;
                const uint32_t addr = Bb + nrow * 128 + ((ch ^ (nrow & 7)) << 4);
                ldsm_x4(bf[jj][0], bf[jj][1], bf[jj + 1][0], bf[jj + 1][1], addr);
            }
#pragma unroll
            for (int i = 0; i < 4; i++)
#pragma unroll
                for (int j = 0; j < 4; j++)
                    mma_f16(acc[i][j], af[i], bf[j]);
        }
        __syncthreads();
    }

    // Epilogue: bias + activation + fp16 store. Boundary at col 512 is
    // block-uniform (BN=128 divides 512).
    const bool is_tanh = (blockN < HH);
#pragma unroll
    for (int i = 0; i < 4; i++) {
        const int row0 = blockM + wm * 64 + i * 16 + g;
#pragma unroll
        for (int j = 0; j < 4; j++) {
            const int col = blockN + wn * 32 + j * 8 + 2 * t;
            const float b0 = bias[col], b1 = bias[col + 1];
            float v[4] = {acc[i][j][0] + b0, acc[i][j][1] + b1,
                          acc[i][j][2] + b0, acc[i][j][3] + b1};
            if (is_tanh) {
#pragma unroll
                for (int q = 0; q < 4; q++) v[q] = tanh_fast(v[q]);
            } else {
#pragma unroll
                for (int q = 0; q < 4; q++) v[q] = sigm_fast(v[q]);
            }
            *(__half2*)&C[(size_t)row0 * N3H + col]       = __floats2half2_rn(v[0], v[1]);
            *(__half2*)&C[(size_t)(row0 + 8) * N3H + col] = __floats2half2_rn(v[2], v[3]);
        }
    }
}

// ---------------------------------------------------------------------------
// fo-pooling scan, both directions in one launch; fp16 in, OutT out.
// One thread per (dir, b, h).
// ---------------------------------------------------------------------------
template <typename OutT>
__global__ void __launch_bounds__(256) scan_kernel(
    const __half* __restrict__ ZFOf,
    const __half* __restrict__ ZFOb,
    OutT* __restrict__ Y)
{
    const int tt  = blockIdx.x * blockDim.x + threadIdx.x;  // 0..16383
    const int dir = tt >> 13;
    const int b   = (tt >> 9) & 15;
    const int h   = tt & 511;

    const __half* __restrict__ Z = dir ? ZFOb : ZFOf;
    const size_t rowBase = (size_t)b * SS;
    const int outOff = dir * HH + h;

    float c = 0.0f;
    constexpr int CH = 8;
    for (int sc = 0; sc < SS; sc += CH) {
        float zv[CH], fv[CH], ov[CH];
#pragma unroll
        for (int j = 0; j < CH; j++) {
            const int s = dir ? (SS - 1 - (sc + j)) : (sc + j);
            const size_t idx = (rowBase + s) * N3H + h;
            zv[j] = __half2float(Z[idx]);
            fv[j] = __half2float(Z[idx + 512]);
            ov[j] = __half2float(Z[idx + 1024]);
        }
#pragma unroll
        for (int j = 0; j < CH; j++) {
            c = fv[j] * c + (1.0f - fv[j]) * zv[j];
            const int s = dir ? (SS - 1 - (sc + j)) : (sc + j);
            Y[(rowBase + s) * OUTC + outOff] = (OutT)(ov[j] * c);
        }
    }
}

// ---------------------------------------------------------------------------
extern "C" void kernel_launch(void* const* d_in, const int* in_sizes, int n_in,
                              void* d_out, int out_size)
{
    const float* X     = (const float*)d_in[0];
    // d_in[1] = seqlens (unused, per reference)
    const float* W_fw0 = (const float*)d_in[2];
    const float* b_fw0 = (const float*)d_in[3];
    const float* W_bw0 = (const float*)d_in[4];
    const float* b_bw0 = (const float*)d_in[5];
    const float* W_fw1 = (const float*)d_in[6];
    const float* b_fw1 = (const float*)d_in[7];
    const float* W_bw1 = (const float*)d_in[8];
    const float* b_bw1 = (const float*)d_in[9];
    float* out = (float*)d_out;

    __half *ZFOf, *ZFOb, *Y1, *Xh, *Wt;
    cudaGetSymbolAddress((void**)&ZFOf, g_ZFO_f);
    cudaGetSymbolAddress((void**)&ZFOb, g_ZFO_b);
    cudaGetSymbolAddress((void**)&Y1,  g_Y1);
    cudaGetSymbolAddress((void**)&Xh,  g_Xh);
    cudaGetSymbolAddress((void**)&Wt,  g_Wt);

    __half* Wt0f = Wt;
    __half* Wt0b = Wt + (size_t)N3H * 1024;
    __half* Wt1f = Wt + (size_t)N3H * 1024 * 2;
    __half* Wt1b = Wt + (size_t)N3H * 1024 * 3;

    cudaFuncSetAttribute(gemm_f16_kernel<DD>,
                         cudaFuncAttributeMaxDynamicSharedMemorySize, SMEM_BYTES);
    cudaFuncSetAttribute(gemm_f16_kernel<OUTC>,
                         cudaFuncAttributeMaxDynamicSharedMemorySize, SMEM_BYTES);

    // Prepass: transpose+fp16 weights, fp16-convert X
    {
        dim3 blk(32, 8);
        transpose_cvt_kernel<<<dim3(DD / 32,  N3H / 32), blk>>>(W_fw0, Wt0f, DD);
        transpose_cvt_kernel<<<dim3(DD / 32,  N3H / 32), blk>>>(W_bw0, Wt0b, DD);
        transpose_cvt_kernel<<<dim3(OUTC / 32, N3H / 32), blk>>>(W_fw1, Wt1f, OUTC);
        transpose_cvt_kernel<<<dim3(OUTC / 32, N3H / 32), blk>>>(W_bw1, Wt1b, OUTC);
        const int n4 = MM * DD / 4;
        cvt_half_kernel<<<(n4 + 255) / 256, 256>>>(X, Xh, n4);
    }

    dim3 gemmGrid(N3H / BN, MM / BM);   // 12 x 256
    dim3 gemmBlock(256);
    dim3 scanGrid(16384 / 256);
    dim3 scanBlock(256);

    // Layer 0
    gemm_f16_kernel<DD><<<gemmGrid, gemmBlock, SMEM_BYTES>>>(Xh, Wt0f, b_fw0, ZFOf);
    gemm_f16_kernel<DD><<<gemmGrid, gemmBlock, SMEM_BYTES>>>(Xh, Wt0b, b_bw0, ZFOb);
    scan_kernel<__half><<<scanGrid, scanBlock>>>(ZFOf, ZFOb, Y1);

    // Layer 1
    gemm_f16_kernel<OUTC><<<gemmGrid, gemmBlock, SMEM_BYTES>>>(Y1, Wt1f, b_fw1, ZFOf);
    gemm_f16_kernel<OUTC><<<gemmGrid, gemmBlock, SMEM_BYTES>>>(Y1, Wt1b, b_bw1, ZFOb);
    scan_kernel<float><<<scanGrid, scanBlock>>>(ZFOf, ZFOb, out);
}

// round 14
// speedup vs baseline: 3.4819x; 1.7116x over previous
#include <cuda_runtime.h>
#include <cuda_fp16.h>
#include <math.h>
#include <stdint.h>

// Problem dims (fixed)
#define BB   16
#define SS   2048
#define DD   512
#define HH   512
#define MM   (BB * SS)    // 32768 rows
#define N3H  1536         // 3*H
#define OUTC 1024         // 2*H

#define BM 128
#define BN 128
#define BK 64
#define NSTAGE 3
#define STAGE_A_BYTES (BM * BK * 2)                 // 16384
#define STAGE_B_BYTES (BN * BK * 2)                 // 16384
#define SMEM_BYTES (NSTAGE * (STAGE_A_BYTES + STAGE_B_BYTES))  // 98304 = 96 KiB

// Scan segmentation
#define NSEG 16
#define SL   (SS / NSEG)        // 128
#define NSEGTH (2 * BB * NSEG * HH)   // 262144

// Scratch (allocation-free rule: __device__ globals)
__device__ __half g_ZFO_f[MM * N3H];         // 96 MiB
__device__ __half g_ZFO_b[MM * N3H];         // 96 MiB
__device__ __half g_Y1[MM * OUTC];           // 64 MiB
__device__ __half g_Xh[MM * DD];             // 32 MiB
__device__ __half g_Wt[4 * N3H * 1024];      // 12 MiB
__device__ float  g_P[NSEGTH];               // 1 MiB  (segment f-products)
__device__ float  g_Cend[NSEGTH];            // 1 MiB  (segment scan-from-0 end state)
__device__ float  g_Cstart[NSEGTH];          // 1 MiB  (fixed-up segment entry state)

// ---------------------------------------------------------------------------
// helpers
// ---------------------------------------------------------------------------
__device__ __forceinline__ float ex2f(float x) {
    float y; asm("ex2.approx.f32 %0, %1;" : "=f"(y) : "f"(x)); return y;
}
__device__ __forceinline__ float rcpf(float x) {
    float y; asm("rcp.approx.f32 %0, %1;" : "=f"(y) : "f"(x)); return y;
}
__device__ __forceinline__ float sigm_fast(float x) {
    return rcpf(1.0f + ex2f(-1.4426950408889634f * x));
}
__device__ __forceinline__ float tanh_fast(float x) {
    return 2.0f * rcpf(1.0f + ex2f(-2.8853900817779268f * x)) - 1.0f;
}
__device__ __forceinline__ void cp16(void* s, const void* g) {
    uint32_t sa = (uint32_t)__cvta_generic_to_shared(s);
    asm volatile("cp.async.cg.shared.global [%0], [%1], 16;" :: "r"(sa), "l"(g));
}
__device__ __forceinline__ void mma_f16(float* c, const uint32_t* a, const uint32_t* b) {
    asm volatile(
        "mma.sync.aligned.m16n8k16.row.col.f32.f16.f16.f32 "
        "{%0,%1,%2,%3}, {%4,%5,%6,%7}, {%8,%9}, {%0,%1,%2,%3};"
        : "+f"(c[0]), "+f"(c[1]), "+f"(c[2]), "+f"(c[3])
        : "r"(a[0]), "r"(a[1]), "r"(a[2]), "r"(a[3]), "r"(b[0]), "r"(b[1]));
}
__device__ __forceinline__ void ldsm_x4(uint32_t& r0, uint32_t& r1, uint32_t& r2,
                                        uint32_t& r3, uint32_t addr) {
    asm volatile("ldmatrix.sync.aligned.m8n8.x4.shared.b16 {%0,%1,%2,%3}, [%4];"
                 : "=r"(r0), "=r"(r1), "=r"(r2), "=r"(r3) : "r"(addr));
}

// ---------------------------------------------------------------------------
// Prepass kernels
// ---------------------------------------------------------------------------
__global__ void transpose_cvt_kernel(const float* __restrict__ W,
                                     __half* __restrict__ Wt, int K)
{
    __shared__ float tile[32][33];
    const int kb = blockIdx.x * 32;
    const int nb = blockIdx.y * 32;
    const int tx = threadIdx.x, ty = threadIdx.y;  // 32 x 8
#pragma unroll
    for (int r = 0; r < 32; r += 8)
        tile[ty + r][tx] = W[(size_t)(kb + ty + r) * N3H + nb + tx];
    __syncthreads();
#pragma unroll
    for (int r = 0; r < 32; r += 8)
        Wt[(size_t)(nb + ty + r) * K + kb + tx] = __float2half_rn(tile[tx][ty + r]);
}

__global__ void cvt_half_kernel(const float* __restrict__ in, __half* __restrict__ out, int n4)
{
    int i = blockIdx.x * blockDim.x + threadIdx.x;
    if (i < n4) {
        float4 v = ((const float4*)in)[i];
        ((__half2*)out)[i * 2]     = __floats2half2_rn(v.x, v.y);
        ((__half2*)out)[i * 2 + 1] = __floats2half2_rn(v.z, v.w);
    }
}

// ---------------------------------------------------------------------------
// FP16 tensor-core GEMM + bias + activation -> fp16 output (as R13)
// ---------------------------------------------------------------------------
template <int K>
__global__ void __launch_bounds__(256, 2) gemm_f16_kernel(
    const __half* __restrict__ A,
    const __half* __restrict__ Bt,     // [1536, K]
    const float* __restrict__ bias,
    __half* __restrict__ C)
{
    extern __shared__ char smem[];
    char* Asm = smem;
    char* Bsm = smem + NSTAGE * STAGE_A_BYTES;
    const uint32_t Asm0 = (uint32_t)__cvta_generic_to_shared(Asm);
    const uint32_t Bsm0 = (uint32_t)__cvta_generic_to_shared(Bsm);

    const int tid = threadIdx.x;
    const int warp = tid >> 5;
    const int lane = tid & 31;
    const int g = lane >> 2;
    const int t = lane & 3;
    const int wm = warp & 1;
    const int wn = warp >> 1;
    const int blockM = blockIdx.y * BM;
    const int blockN = blockIdx.x * BN;

    const int lrow = lane & 7;
    const int sel  = lane >> 3;
    const int a_mrow_off = lrow + (sel & 1) * 8;
    const int a_choff    = sel >> 1;
    const int b_nrow_off = lrow + (sel >> 1) * 8;
    const int b_choff    = sel & 1;

    float acc[4][4][4];
#pragma unroll
    for (int i = 0; i < 4; i++)
#pragma unroll
        for (int j = 0; j < 4; j++)
#pragma unroll
            for (int q = 0; q < 4; q++) acc[i][j][q] = 0.0f;

    auto load_stage = [&](int buf, int k0) {
#pragma unroll
        for (int it = 0; it < 4; it++) {
            const int idx = tid + it * 256;
            const int row = idx >> 3;
            const int c4  = idx & 7;
            const int off = row * 128 + ((c4 ^ (row & 7)) << 4);
            cp16(Asm + buf * STAGE_A_BYTES + off,
                 &A[(size_t)(blockM + row) * K + k0 + c4 * 8]);
        }
#pragma unroll
        for (int it = 0; it < 4; it++) {
            const int idx = tid + it * 256;
            const int row = idx >> 3;
            const int c4  = idx & 7;
            const int off = row * 128 + ((c4 ^ (row & 7)) << 4);
            cp16(Bsm + buf * STAGE_B_BYTES + off,
                 &Bt[(size_t)(blockN + row) * K + k0 + c4 * 8]);
        }
        asm volatile("cp.async.commit_group;" ::: "memory");
    };

    const int ntiles = K / BK;
    load_stage(0, 0);
    load_stage(1, BK);

    for (int kt = 0; kt < ntiles; kt++) {
        if (kt + 2 < ntiles) {
            load_stage((kt + 2) % NSTAGE, (kt + 2) * BK);
            asm volatile("cp.async.wait_group 2;" ::: "memory");
        } else if (kt + 1 < ntiles) {
            asm volatile("cp.async.wait_group 1;" ::: "memory");
        } else {
            asm volatile("cp.async.wait_group 0;" ::: "memory");
        }
        __syncthreads();

        const uint32_t Ab = Asm0 + (kt % NSTAGE) * STAGE_A_BYTES;
        const uint32_t Bb = Bsm0 + (kt % NSTAGE) * STAGE_B_BYTES;

#pragma unroll
        for (int kk = 0; kk < BK; kk += 16) {
            const int ch0 = kk >> 3;
            uint32_t af[4][4], bf[4][2];
#pragma unroll
            for (int i = 0; i < 4; i++) {
                const int mrow = wm * 64 + i * 16 + a_mrow_off;
                const int ch   = ch0 + a_choff;
                const uint32_t addr = Ab + mrow * 128 + ((ch ^ (mrow & 7)) << 4);
                ldsm_x4(af[i][0], af[i][1], af[i][2], af[i][3], addr);
            }
#pragma unroll
            for (int jj = 0; jj < 4; jj += 2) {
                const int nrow = wn * 32 + jj * 8 + b_nrow_off;
                const int ch   = ch0 + b_choff;
                const uint32_t addr = Bb + nrow * 128 + ((ch ^ (nrow & 7)) << 4);
                ldsm_x4(bf[jj][0], bf[jj][1], bf[jj + 1][0], bf[jj + 1][1], addr);
            }
#pragma unroll
            for (int i = 0; i < 4; i++)
#pragma unroll
                for (int j = 0; j < 4; j++)
                    mma_f16(acc[i][j], af[i], bf[j]);
        }
        __syncthreads();
    }

    const bool is_tanh = (blockN < HH);
#pragma unroll
    for (int i = 0; i < 4; i++) {
        const int row0 = blockM + wm * 64 + i * 16 + g;
#pragma unroll
        for (int j = 0; j < 4; j++) {
            const int col = blockN + wn * 32 + j * 8 + 2 * t;
            const float b0 = bias[col], b1 = bias[col + 1];
            float v[4] = {acc[i][j][0] + b0, acc[i][j][1] + b1,
                          acc[i][j][2] + b0, acc[i][j][3] + b1};
            if (is_tanh) {
#pragma unroll
                for (int q = 0; q < 4; q++) v[q] = tanh_fast(v[q]);
            } else {
#pragma unroll
                for (int q = 0; q < 4; q++) v[q] = sigm_fast(v[q]);
            }
            *(__half2*)&C[(size_t)row0 * N3H + col]       = __floats2half2_rn(v[0], v[1]);
            *(__half2*)&C[(size_t)(row0 + 8) * N3H + col] = __floats2half2_rn(v[2], v[3]);
        }
    }
}

// ---------------------------------------------------------------------------
// Parallel fo-pooling scan: 3 passes.
// Linear recurrence c_j = f_j c_{j-1} + (1-f_j) z_j is composable: a segment
// maps c_in -> P*c_in + Cend with P = prod(f).
// Logical step j in [0,SS); physical s = j (fwd) or SS-1-j (bwd).
// Pass A: per (dir,b,seg,h), scan segment from c=0 -> (P, Cend). 262144 thr.
// Pass B: per (dir,b,h), chain 16 segments -> Cstart. 16384 thr.
// Pass C: per (dir,b,seg,h), re-scan from Cstart, apply o, write Y.
// ---------------------------------------------------------------------------
__global__ void __launch_bounds__(256) scan_partial_kernel(
    const __half* __restrict__ ZFOf,
    const __half* __restrict__ ZFOb,
    float* __restrict__ P,
    float* __restrict__ Cend)
{
    const int tt  = blockIdx.x * blockDim.x + threadIdx.x;  // 0..262143
    const int h   = tt & 511;
    const int seg = (tt >> 9) & 15;
    const int b   = (tt >> 13) & 15;
    const int dir = tt >> 17;

    const __half* __restrict__ Z = dir ? ZFOb : ZFOf;
    const size_t rowBase = (size_t)b * SS;
    const int j0 = seg * SL;

    float c = 0.0f, p = 1.0f;
    constexpr int CH = 8;
    for (int sc = 0; sc < SL; sc += CH) {
        float zv[CH], fv[CH];
#pragma unroll
        for (int q = 0; q < CH; q++) {
            const int j = j0 + sc + q;
            const int s = dir ? (SS - 1 - j) : j;
            const size_t idx = (rowBase + s) * N3H + h;
            zv[q] = __half2float(Z[idx]);
            fv[q] = __half2float(Z[idx + 512]);
        }
#pragma unroll
        for (int q = 0; q < CH; q++) {
            c = fv[q] * c + (1.0f - fv[q]) * zv[q];
            p *= fv[q];
        }
    }
    P[tt] = p;
    Cend[tt] = c;
}

__global__ void __launch_bounds__(256) scan_fix_kernel(
    const float* __restrict__ P,
    const float* __restrict__ Cend,
    float* __restrict__ Cstart)
{
    const int tt  = blockIdx.x * blockDim.x + threadIdx.x;  // 0..16383
    const int h   = tt & 511;
    const int b   = (tt >> 9) & 15;
    const int dir = tt >> 13;

    const int base = ((dir * BB + b) * NSEG) * 512 + h;
    float c = 0.0f;
#pragma unroll
    for (int seg = 0; seg < NSEG; seg++) {
        const int id = base + seg * 512;
        Cstart[id] = c;
        c = P[id] * c + Cend[id];
    }
}

template <typename OutT>
__global__ void __launch_bounds__(256) scan_final_kernel(
    const __half* __restrict__ ZFOf,
    const __half* __restrict__ ZFOb,
    const float* __restrict__ Cstart,
    OutT* __restrict__ Y)
{
    const int tt  = blockIdx.x * blockDim.x + threadIdx.x;  // 0..262143
    const int h   = tt & 511;
    const int seg = (tt >> 9) & 15;
    const int b   = (tt >> 13) & 15;
    const int dir = tt >> 17;

    const __half* __restrict__ Z = dir ? ZFOb : ZFOf;
    const size_t rowBase = (size_t)b * SS;
    const int j0 = seg * SL;
    const int outOff = dir * HH + h;

    float c = Cstart[tt];
    constexpr int CH = 8;
    for (int sc = 0; sc < SL; sc += CH) {
        float zv[CH], fv[CH], ov[CH];
        int sphys[CH];
#pragma unroll
        for (int q = 0; q < CH; q++) {
            const int j = j0 + sc + q;
            const int s = dir ? (SS - 1 - j) : j;
            sphys[q] = s;
            const size_t idx = (rowBase + s) * N3H + h;
            zv[q] = __half2float(Z[idx]);
            fv[q] = __half2float(Z[idx + 512]);
            ov[q] = __half2float(Z[idx + 1024]);
        }
#pragma unroll
        for (int q = 0; q < CH; q++) {
            c = fv[q] * c + (1.0f - fv[q]) * zv[q];
            Y[(rowBase + sphys[q]) * OUTC + outOff] = (OutT)(ov[q] * c);
        }
    }
}

// ---------------------------------------------------------------------------
extern "C" void kernel_launch(void* const* d_in, const int* in_sizes, int n_in,
                              void* d_out, int out_size)
{
    const float* X     = (const float*)d_in[0];
    // d_in[1] = seqlens (unused, per reference)
    const float* W_fw0 = (const float*)d_in[2];
    const float* b_fw0 = (const float*)d_in[3];
    const float* W_bw0 = (const float*)d_in[4];
    const float* b_bw0 = (const float*)d_in[5];
    const float* W_fw1 = (const float*)d_in[6];
    const float* b_fw1 = (const float*)d_in[7];
    const float* W_bw1 = (const float*)d_in[8];
    const float* b_bw1 = (const float*)d_in[9];
    float* out = (float*)d_out;

    __half *ZFOf, *ZFOb, *Y1, *Xh, *Wt;
    float *P, *Cend, *Cstart;
    cudaGetSymbolAddress((void**)&ZFOf, g_ZFO_f);
    cudaGetSymbolAddress((void**)&ZFOb, g_ZFO_b);
    cudaGetSymbolAddress((void**)&Y1,  g_Y1);
    cudaGetSymbolAddress((void**)&Xh,  g_Xh);
    cudaGetSymbolAddress((void**)&Wt,  g_Wt);
    cudaGetSymbolAddress((void**)&P,      g_P);
    cudaGetSymbolAddress((void**)&Cend,   g_Cend);
    cudaGetSymbolAddress((void**)&Cstart, g_Cstart);

    __half* Wt0f = Wt;
    __half* Wt0b = Wt + (size_t)N3H * 1024;
    __half* Wt1f = Wt + (size_t)N3H * 1024 * 2;
    __half* Wt1b = Wt + (size_t)N3H * 1024 * 3;

    cudaFuncSetAttribute(gemm_f16_kernel<DD>,
                         cudaFuncAttributeMaxDynamicSharedMemorySize, SMEM_BYTES);
    cudaFuncSetAttribute(gemm_f16_kernel<OUTC>,
                         cudaFuncAttributeMaxDynamicSharedMemorySize, SMEM_BYTES);

    // Prepass: transpose+fp16 weights, fp16-convert X
    {
        dim3 blk(32, 8);
        transpose_cvt_kernel<<<dim3(DD / 32,  N3H / 32), blk>>>(W_fw0, Wt0f, DD);
        transpose_cvt_kernel<<<dim3(DD / 32,  N3H / 32), blk>>>(W_bw0, Wt0b, DD);
        transpose_cvt_kernel<<<dim3(OUTC / 32, N3H / 32), blk>>>(W_fw1, Wt1f, OUTC);
        transpose_cvt_kernel<<<dim3(OUTC / 32, N3H / 32), blk>>>(W_bw1, Wt1b, OUTC);
        const int n4 = MM * DD / 4;
        cvt_half_kernel<<<(n4 + 255) / 256, 256>>>(X, Xh, n4);
    }

    dim3 gemmGrid(N3H / BN, MM / BM);   // 12 x 256
    dim3 gemmBlock(256);
    const int segGrid = NSEGTH / 256;   // 1024
    const int fixGrid = 16384 / 256;    // 64

    // Layer 0
    gemm_f16_kernel<DD><<<gemmGrid, gemmBlock, SMEM_BYTES>>>(Xh, Wt0f, b_fw0, ZFOf);
    gemm_f16_kernel<DD><<<gemmGrid, gemmBlock, SMEM_BYTES>>>(Xh, Wt0b, b_bw0, ZFOb);
    scan_partial_kernel<<<segGrid, 256>>>(ZFOf, ZFOb, P, Cend);
    scan_fix_kernel<<<fixGrid, 256>>>(P, Cend, Cstart);
    scan_final_kernel<__half><<<segGrid, 256>>>(ZFOf, ZFOb, Cstart, Y1);

    // Layer 1
    gemm_f16_kernel<OUTC><<<gemmGrid, gemmBlock, SMEM_BYTES>>>(Y1, Wt1f, b_fw1, ZFOf);
    gemm_f16_kernel<OUTC><<<gemmGrid, gemmBlock, SMEM_BYTES>>>(Y1, Wt1b, b_bw1, ZFOb);
    scan_partial_kernel<<<segGrid, 256>>>(ZFOf, ZFOb, P, Cend);
    scan_fix_kernel<<<fixGrid, 256>>>(P, Cend, Cstart);
    scan_final_kernel<float><<<segGrid, 256>>>(ZFOf, ZFOb, Cstart, out);
}